// round 12
// baseline (speedup 1.0000x reference)
#include <cuda_runtime.h>
#include <cuda_fp16.h>
#include <cstdint>

#define BB 2
#define CC 256
#define HH 48
#define WW 48
#define HWP 2304
#define DM 256
#define NH 8
#define DK 32
#define QK_SCALE 0.17677669529663689f   // 1/sqrt(32)
#define LOG2E 1.4426950408889634f
#define EXP_OFF 7.0f                     // p scaled by 2^-7; cancels in softmax
#define QPAD 40                          // f16 pitch = 80B (16B multiple)
#define WPAD 40
#define BPITCH 80                        // bias tile pitch bytes
#define NSPLIT 2
#define NTILE (HWP / 64)                 // 36
#define TPS (NTILE / NSPLIT)             // 18 tiles per split

// ---------------- scratch (allocation-free) ----------------
__device__ __half g_Qh[BB * HWP * DM];
__device__ __half g_Kh[BB * HWP * DM];
__device__ __half g_Vh[BB * HWP * DM];
__device__ __half g_Oph[NSPLIT * BB * HWP * DM];   // partial attention out
__device__ float  g_rsP[NSPLIT * BB * NH * HWP];   // partial row sums
__device__ __half g_Oh[BB * HWP * DM];             // combined attention out
__device__ __half g_xh[BB * HWP * CC];             // x transposed (b,p,c)
__device__ __half g_Wqh[DM * CC];
__device__ __half g_Wkh[DM * CC];
__device__ __half g_Wvh[DM * CC];
__device__ __half g_Woh[CC * DM];
__device__ unsigned char g_dtab[95 * 95];
__device__ unsigned char g_biasF8[HWP * HWP];

// ---------------- helpers ----------------
__device__ __forceinline__ uint32_t smem_u32(const void* p) {
    uint32_t a;
    asm("{ .reg .u64 t; cvta.to.shared.u64 t, %1; cvt.u32.u64 %0, t; }" : "=r"(a) : "l"(p));
    return a;
}
__device__ __forceinline__ void ldmx4(uint32_t& r0, uint32_t& r1, uint32_t& r2, uint32_t& r3, uint32_t a) {
    asm volatile("ldmatrix.sync.aligned.m8n8.x4.shared.b16 {%0,%1,%2,%3}, [%4];"
                 : "=r"(r0), "=r"(r1), "=r"(r2), "=r"(r3) : "r"(a));
}
__device__ __forceinline__ void ldmx4t(uint32_t& r0, uint32_t& r1, uint32_t& r2, uint32_t& r3, uint32_t a) {
    asm volatile("ldmatrix.sync.aligned.m8n8.x4.trans.shared.b16 {%0,%1,%2,%3}, [%4];"
                 : "=r"(r0), "=r"(r1), "=r"(r2), "=r"(r3) : "r"(a));
}
__device__ __forceinline__ void mma16816f(float* c, const uint32_t* a, const uint32_t* b) {
    asm volatile("mma.sync.aligned.m16n8k16.row.col.f32.f16.f16.f32 "
                 "{%0,%1,%2,%3},{%4,%5,%6,%7},{%8,%9},{%0,%1,%2,%3};"
                 : "+f"(c[0]), "+f"(c[1]), "+f"(c[2]), "+f"(c[3])
                 : "r"(a[0]), "r"(a[1]), "r"(a[2]), "r"(a[3]), "r"(b[0]), "r"(b[1]));
}
__device__ __forceinline__ void mma16816h(uint32_t* d, const uint32_t* a, uint32_t b0, uint32_t b1) {
    asm volatile("mma.sync.aligned.m16n8k16.row.col.f16.f16.f16.f16 "
                 "{%0,%1},{%2,%3,%4,%5},{%6,%7},{%0,%1};"
                 : "+r"(d[0]), "+r"(d[1])
                 : "r"(a[0]), "r"(a[1]), "r"(a[2]), "r"(a[3]), "r"(b0), "r"(b1));
}
__device__ __forceinline__ uint32_t f2h2(float lo, float hi) {
    __half2 h = __floats2half2_rn(lo, hi);
    return *(uint32_t*)&h;
}
__device__ __forceinline__ uint32_t hfma2u(uint32_t a, uint32_t b, uint32_t c) {
    uint32_t d;
    asm("fma.rn.f16x2 %0, %1, %2, %3;" : "=r"(d) : "r"(a), "r"(b), "r"(c));
    return d;
}
__device__ __forceinline__ uint32_t hadd2u(uint32_t a, uint32_t b) {
    uint32_t d;
    asm("add.rn.f16x2 %0, %1, %2;" : "=r"(d) : "r"(a), "r"(b));
    return d;
}
__device__ __forceinline__ uint32_t hex2u(uint32_t a) {
    uint32_t d;
    asm("ex2.approx.f16x2 %0, %1;" : "=r"(d) : "r"(a));
    return d;
}
__device__ __forceinline__ float2 h2f2(uint32_t u) {
    __half2 h = *(__half2*)&u;
    return __half22float2(h);
}
#define CPA16(dst, src) asm volatile("cp.async.cg.shared.global [%0], [%1], 16;" :: "r"(dst), "l"(src))
#define CPA_COMMIT()    asm volatile("cp.async.commit_group;")
#define CPA_WAIT0()     asm volatile("cp.async.wait_group 0;")

// ---------------------------------------------------------------------------
// Prep A (merged): blocks [0,512): W fp32->f16; blocks [512,548): dtab.
// ---------------------------------------------------------------------------
__global__ __launch_bounds__(256) void prep_kernel(
    const float* __restrict__ lam_p,
    const float* __restrict__ Wq, const float* __restrict__ Wk,
    const float* __restrict__ Wv, const float* __restrict__ Wo)
{
    const int bx = blockIdx.x;
    if (bx < 512) {
        const int idx = bx * 256 + threadIdx.x;
        const int mat = idx >> 15;
        const int off = idx & 32767;
        const float* s = (mat == 0) ? Wq : ((mat == 1) ? Wk : ((mat == 2) ? Wv : Wo));
        uint32_t* d = (uint32_t*)((mat == 0) ? g_Wqh : ((mat == 1) ? g_Wkh : ((mat == 2) ? g_Wvh : g_Woh)));
        d[off] = f2h2(s[off * 2], s[off * 2 + 1]);
    } else {
        const int idx = (bx - 512) * 256 + threadIdx.x;
        if (idx >= 95 * 95) return;
        const float lam2 = (*lam_p) * LOG2E;
        const int dy = idx / 95 - 47;
        const int dx = idx % 95 - 47;
        const float t = lam2 * __expf(-sqrtf((float)(dy * dy + dx * dx)));
        unsigned short u;
        asm("cvt.rn.satfinite.e4m3x2.f32 %0, %1, %2;" : "=h"(u) : "f"(t), "f"(t));
        g_dtab[idx] = (unsigned char)(u & 0xFF);
    }
}

// ---------------------------------------------------------------------------
// Prep B: expand bias matrix by table lookup.
// ---------------------------------------------------------------------------
__global__ __launch_bounds__(256) void bias_fill_kernel()
{
    const int idx = blockIdx.x * 256 + threadIdx.x;
    const int i  = idx / (HWP / 4);
    const int j0 = (idx - i * (HWP / 4)) * 4;
    const int yi = i / WW, xi = i - yi * WW;
    uint32_t out = 0;
    #pragma unroll
    for (int u = 0; u < 4; u++) {
        const int j  = j0 + u;
        const int yj = j / WW;
        const int xj = j - yj * WW;
        const int ti = (yi - yj + 47) * 95 + (xi - xj + 47);
        out |= (uint32_t)g_dtab[ti] << (u * 8);
    }
    ((uint32_t*)g_biasF8)[idx] = out;
}

// ---------------------------------------------------------------------------
// Prep C: transpose+convert x (b,c,p) fp32 -> g_xh (b,p,c) f16 (vectorized).
// ---------------------------------------------------------------------------
__global__ __launch_bounds__(256) void xt_kernel(const float* __restrict__ x)
{
    __shared__ float ts[64][65];
    const int b  = blockIdx.z;
    const int pB = blockIdx.x * 64;
    const int cB = blockIdx.y * 64;
    #pragma unroll
    for (int i = threadIdx.x; i < 1024; i += 256) {
        const int c  = i >> 4;
        const int pq = (i & 15) * 4;
        const float4 v = *(const float4*)&x[((size_t)b * CC + cB + c) * HWP + pB + pq];
        ts[c][pq + 0] = v.x;
        ts[c][pq + 1] = v.y;
        ts[c][pq + 2] = v.z;
        ts[c][pq + 3] = v.w;
    }
    __syncthreads();
    #pragma unroll
    for (int i = threadIdx.x; i < 1024; i += 256) {
        const int p  = i >> 4;
        const int cq = (i & 15) * 4;
        uint2 o;
        o.x = f2h2(ts[cq + 0][p], ts[cq + 1][p]);
        o.y = f2h2(ts[cq + 2][p], ts[cq + 3][p]);
        *(uint2*)(g_xh + ((size_t)(b * HWP + pB + p) * CC + cB + cq)) = o;
    }
}

// ---------------------------------------------------------------------------
// Kernel 1: HMMA fused QKV + pe + bias, 2-stage cp.async (unchanged).
// ---------------------------------------------------------------------------
__global__ __launch_bounds__(256) void qkv_mma_kernel(
    const float* __restrict__ bq, const float* __restrict__ bk, const float* __restrict__ bv)
{
    __shared__ __align__(16) __half As[2][64 * QPAD];
    __shared__ __align__(16) __half Ws[2][3][64 * WPAD];

    const int tid  = threadIdx.x;
    const int warp = tid >> 5;
    const int lane = tid & 31;

    const int gp    = blockIdx.x * 64;
    const int b     = gp / HWP;
    const int pb    = gp - b * HWP;
    const int dBase = blockIdx.y * 64;
    const bool use_y = (dBase >= 128);

    const uint32_t asA = smem_u32(As);
    const uint32_t wsA = smem_u32(Ws);

    const __half* gW[3] = { g_Wqh, g_Wkh, g_Wvh };

    auto load_chunk = [&](int s, int c0) {
        const char* ab = (const char*)g_xh + ((size_t)(b * HWP + pb) * CC + c0) * 2;
        {
            const int i = tid;
            const int r = i >> 2, q = i & 3;
            CPA16(asA + s * 5120 + r * 80 + q * 16, ab + (size_t)r * (CC * 2) + q * 16);
        }
        #pragma unroll
        for (int i = tid; i < 768; i += 256) {
            const int mat = i / 256;
            const int rem = i - mat * 256;
            const int r = rem >> 2, q = rem & 3;
            const char* wb = (const char*)gW[mat] + ((size_t)(dBase + r) * CC + c0) * 2;
            CPA16(wsA + s * 15360 + mat * 5120 + r * 80 + q * 16, wb + q * 16);
        }
        CPA_COMMIT();
    };

    const int mw = warp >> 2;
    const int nw = warp & 3;

    float acc[3][2][2][4] = {};

    load_chunk(0, 0);

    for (int c = 0; c < 8; c++) {
        CPA_WAIT0();
        __syncthreads();
        if (c < 7) load_chunk((c + 1) & 1, (c + 1) * 32);

        const int s = c & 1;
        const __half* Ab = As[s];

        const int arow = (lane & 7) + ((lane >> 3) & 1) * 8;
        const int acol = (lane >> 4) * 8;
        const int brow = (lane & 7) + ((lane >> 4) & 1) * 8;
        const int bcol = ((lane >> 3) & 1) * 8;

        #pragma unroll
        for (int ks = 0; ks < 2; ks++) {
            uint32_t af[2][4];
            #pragma unroll
            for (int mt = 0; mt < 2; mt++) {
                uint32_t a = smem_u32(Ab + (mw * 32 + mt * 16 + arow) * QPAD + ks * 16 + acol);
                ldmx4(af[mt][0], af[mt][1], af[mt][2], af[mt][3], a);
            }
            #pragma unroll
            for (int mat = 0; mat < 3; mat++) {
                uint32_t bf[4];
                uint32_t a = smem_u32(&Ws[s][mat][(nw * 16 + brow) * WPAD + ks * 16 + bcol]);
                ldmx4(bf[0], bf[1], bf[2], bf[3], a);
                #pragma unroll
                for (int mt = 0; mt < 2; mt++) {
                    mma16816f(acc[mat][mt][0], af[mt], bf);
                    mma16816f(acc[mat][mt][1], af[mt], bf + 2);
                }
            }
        }
    }

    __syncthreads();
    __half* pes = (__half*)As;
    for (int i = tid; i < 48 * 64; i += 256) {
        const int coord = i >> 6;
        const int dloc  = i & 63;
        const int dl    = (dBase + dloc) - (use_y ? 128 : 0);
        const float freq = __expf(-(float)(dl >> 1) * 0.14391156642875743f);
        const float arg  = (float)coord * freq;
        pes[i] = __float2half((dl & 1) ? __cosf(arg) : __sinf(arg));
    }
    __syncthreads();

    const int c2 = 2 * (lane & 3);
    #pragma unroll
    for (int mt = 0; mt < 2; mt++) {
        #pragma unroll
        for (int rr = 0; rr < 2; rr++) {
            const int ploc = mw * 32 + mt * 16 + (lane >> 2) + rr * 8;
            const int p    = pb + ploc;
            const int coord = use_y ? (p / WW) : (p % WW);
            const size_t rowIdx = ((size_t)b * HWP + p) * DM + dBase;
            #pragma unroll
            for (int nt = 0; nt < 2; nt++) {
                const int dloc = nw * 16 + nt * 8 + c2;
                const int d    = dBase + dloc;
                const float pe0 = __half2float(pes[coord * 64 + dloc]);
                const float pe1 = __half2float(pes[coord * 64 + dloc + 1]);
                const float q0 = acc[0][mt][nt][rr * 2 + 0] + bq[d]     + pe0;
                const float q1 = acc[0][mt][nt][rr * 2 + 1] + bq[d + 1] + pe1;
                const float k0 = acc[1][mt][nt][rr * 2 + 0] + bk[d]     + pe0;
                const float k1 = acc[1][mt][nt][rr * 2 + 1] + bk[d + 1] + pe1;
                const float v0 = acc[2][mt][nt][rr * 2 + 0] + bv[d];
                const float v1 = acc[2][mt][nt][rr * 2 + 1] + bv[d + 1];
                *(uint32_t*)(g_Qh + rowIdx + dloc) = f2h2(q0, q1);
                *(uint32_t*)(g_Kh + rowIdx + dloc) = f2h2(k0, k1);
                *(uint32_t*)(g_Vh + rowIdx + dloc) = f2h2(v0, v1);
            }
        }
    }
}

// ---------------------------------------------------------------------------
// Kernel 2: f16 HMMA flash attention, key-split warps.
// CTA 256 thr = 8 warps: wm = warp>>1 (4 row-groups of 32), wk = warp&1
// (key half of each 64-key tile). Grid (18, 16, NSPLIT).
// ---------------------------------------------------------------------------
__global__ __launch_bounds__(256, 4) void attn_mma_kernel()
{
    __shared__ __align__(16) __half Qs[128 * QPAD];             // 10240B
    __shared__ __align__(16) __half Ks[2][64 * QPAD];           // 10240B
    __shared__ __align__(16) __half Vs[2][64 * QPAD];           // 10240B
    __shared__ __align__(16) unsigned char Bs[2][128 * BPITCH]; // 20480B

    const int tid  = threadIdx.x;
    const int warp = tid >> 5;
    const int lane = tid & 31;
    const int wm   = warp >> 1;     // row group: rows wm*32..+32
    const int wk   = warp & 1;      // key half: keys wk*32..+32 within tile
    const int b    = blockIdx.y >> 3;
    const int h    = blockIdx.y & 7;
    const int rowBase = blockIdx.x * 128;
    const int z    = blockIdx.z;
    const int tBeg = z * TPS;

    const uint32_t ksA = smem_u32(Ks);
    const uint32_t vsA = smem_u32(Vs);
    const uint32_t bsA = smem_u32(Bs);

    auto issue_tile = [&](int t, int s) {
        const int jt = t * 64;
        const char* kb = (const char*)g_Kh + ((size_t)(b * HWP + jt) * DM + h * DK) * 2;
        const char* vb = (const char*)g_Vh + ((size_t)(b * HWP + jt) * DM + h * DK) * 2;
        {
            const int i = tid;  // 256 chunks each
            const int r = i >> 2, q = i & 3;
            CPA16(ksA + s * 5120 + r * 80 + q * 16, kb + (size_t)r * (DM * 2) + q * 16);
            CPA16(vsA + s * 5120 + r * 80 + q * 16, vb + (size_t)r * (DM * 2) + q * 16);
        }
        const unsigned char* bb = g_biasF8 + (size_t)rowBase * HWP + jt;
        #pragma unroll
        for (int i = tid; i < 512; i += 256) {
            const int r = i >> 2, q = i & 3;
            CPA16(bsA + s * 10240 + r * BPITCH + q * 16, bb + (size_t)r * HWP + q * 16);
        }
        CPA_COMMIT();
    };

    // Q tile (128 rows x 32 dims)
    {
        const __half* qsrc = g_Qh + (size_t)(b * HWP + rowBase) * DM + h * DK;
        #pragma unroll
        for (int i = tid; i < 512; i += 256) {
            const int r = i >> 2, q = i & 3;
            *(uint4*)(Qs + r * QPAD + q * 8) = *(const uint4*)(qsrc + (size_t)r * DM + q * 8);
        }
    }
    issue_tile(tBeg, 0);
    __syncthreads();

    // Q fragments for rows wm*32..+32
    uint32_t qa[2][2][4];
    {
        const int arow = (lane & 7) + ((lane >> 3) & 1) * 8;
        const int acol = (lane >> 4) * 8;
        #pragma unroll
        for (int m = 0; m < 2; m++)
            #pragma unroll
            for (int ks = 0; ks < 2; ks++) {
                uint32_t a = smem_u32(Qs + (wm * 32 + m * 16 + arow) * QPAD + ks * 16 + acol);
                ldmx4(qa[m][ks][0], qa[m][ks][1], qa[m][ks][2], qa[m][ks][3], a);
            }
    }

    const int c2 = 2 * (lane & 3);
    int boff[2][2];
    #pragma unroll
    for (int m = 0; m < 2; m++)
        #pragma unroll
        for (int rr = 0; rr < 2; rr++)
            boff[m][rr] = (wm * 32 + m * 16 + (lane >> 2) + rr * 8) * BPITCH + wk * 32 + c2;

    const uint32_t SC2h = f2h2(QK_SCALE * LOG2E, QK_SCALE * LOG2E);
    const uint32_t NEGO = f2h2(-EXP_OFF, -EXP_OFF);

    uint32_t o[2][4][2];
    uint32_t rsum2[2][2];
    #pragma unroll
    for (int m = 0; m < 2; m++) {
        #pragma unroll
        for (int n = 0; n < 4; n++) { o[m][n][0] = 0u; o[m][n][1] = 0u; }
        rsum2[m][0] = 0u; rsum2[m][1] = 0u;
    }

    for (int t = 0; t < TPS; t++) {
        CPA_WAIT0();
        __syncthreads();
        if (t < TPS - 1) issue_tile(tBeg + t + 1, (t + 1) & 1);
        const int s = t & 1;

        // --- S = Q K^T over this warp's 32 keys (4 n8 tiles) ---
        uint32_t S[2][4][2];
        #pragma unroll
        for (int m = 0; m < 2; m++)
            #pragma unroll
            for (int n = 0; n < 4; n++) { S[m][n][0] = 0u; S[m][n][1] = 0u; }
        {
            const int brow = (lane & 7) + ((lane >> 4) & 1) * 8;
            const int bcol = ((lane >> 3) & 1) * 8;
            #pragma unroll
            for (int np = 0; np < 2; np++) {
                #pragma unroll
                for (int ks = 0; ks < 2; ks++) {
                    uint32_t kf[4];
                    uint32_t a = smem_u32(&Ks[s][(wk * 32 + np * 16 + brow) * QPAD + ks * 16 + bcol]);
                    ldmx4(kf[0], kf[1], kf[2], kf[3], a);
                    #pragma unroll
                    for (int m = 0; m < 2; m++) {
                        mma16816h(S[m][2 * np],     qa[m][ks], kf[0], kf[1]);
                        mma16816h(S[m][2 * np + 1], qa[m][ks], kf[2], kf[3]);
                    }
                }
            }
        }

        // --- P = 2^(S*c + bias - OFF) ---
        const unsigned char* bbuf = Bs[s];
        #pragma unroll
        for (int n = 0; n < 4; n++) {
            #pragma unroll
            for (int m = 0; m < 2; m++) {
                const unsigned short h0 = *(const unsigned short*)(bbuf + boff[m][0] + n * 8);
                const unsigned short h1 = *(const unsigned short*)(bbuf + boff[m][1] + n * 8);
                uint32_t b0, b1;
                asm("cvt.rn.f16x2.e4m3x2 %0, %1;" : "=r"(b0) : "h"(h0));
                asm("cvt.rn.f16x2.e4m3x2 %0, %1;" : "=r"(b1) : "h"(h1));
                b0 = hadd2u(b0, NEGO);
                b1 = hadd2u(b1, NEGO);
                S[m][n][0] = hex2u(hfma2u(S[m][n][0], SC2h, b0));
                S[m][n][1] = hex2u(hfma2u(S[m][n][1], SC2h, b1));
                rsum2[m][0] = hadd2u(rsum2[m][0], S[m][n][0]);
                rsum2[m][1] = hadd2u(rsum2[m][1], S[m][n][1]);
            }
        }

        // --- O += P @ V over this warp's 32 keys ---
        {
            const int vrow = (lane & 7) + ((lane >> 3) & 1) * 8;
            const int vcol = ((lane >> 4) & 1) * 8;
            #pragma unroll
            for (int k2 = 0; k2 < 2; k2++) {
                #pragma unroll
                for (int dp = 0; dp < 2; dp++) {
                    uint32_t vf[4];
                    uint32_t a = smem_u32(&Vs[s][(wk * 32 + k2 * 16 + vrow) * QPAD + dp * 16 + vcol]);
                    ldmx4t(vf[0], vf[1], vf[2], vf[3], a);
                    #pragma unroll
                    for (int m = 0; m < 2; m++) {
                        mma16816h(o[m][2 * dp],     &S[m][2 * k2][0], vf[0], vf[1]);
                        mma16816h(o[m][2 * dp + 1], &S[m][2 * k2][0], vf[2], vf[3]);
                    }
                }
            }
        }
    }

    // ---- merge wk halves via smem (reuse Ks/Vs buffers) ----
    // fold rsum to per-row floats (all lanes hold quad sum)
    float rs[2][2];
    #pragma unroll
    for (int m = 0; m < 2; m++)
        #pragma unroll
        for (int rr = 0; rr < 2; rr++) {
            float2 f = h2f2(rsum2[m][rr]);
            float sv = f.x + f.y;
            sv += __shfl_xor_sync(0xFFFFFFFF, sv, 1);
            sv += __shfl_xor_sync(0xFFFFFFFF, sv, 2);
            rs[m][rr] = sv;
        }

    __syncthreads();   // all warps done with Ks/Vs
    uint32_t* xch = (uint32_t*)Ks;   // 4 warps x 32 lanes x 16 u32 = 8192B
    float*    xrs = (float*)Vs;      // 128 floats

    if (wk == 1) {
        const int base = (wm * 32 + lane) * 16;
        #pragma unroll
        for (int m = 0; m < 2; m++)
            #pragma unroll
            for (int n = 0; n < 4; n++) {
                xch[base + m * 8 + n * 2 + 0] = o[m][n][0];
                xch[base + m * 8 + n * 2 + 1] = o[m][n][1];
            }
        if ((lane & 3) == 0) {
            #pragma unroll
            for (int m = 0; m < 2; m++)
                #pragma unroll
                for (int rr = 0; rr < 2; rr++)
                    xrs[wm * 32 + m * 16 + (lane >> 2) + rr * 8] = rs[m][rr];
        }
    }
    __syncthreads();

    if (wk == 0) {
        const int base = (wm * 32 + lane) * 16;
        #pragma unroll
        for (int m = 0; m < 2; m++)
            #pragma unroll
            for (int n = 0; n < 4; n++) {
                o[m][n][0] = hadd2u(o[m][n][0], xch[base + m * 8 + n * 2 + 0]);
                o[m][n][1] = hadd2u(o[m][n][1], xch[base + m * 8 + n * 2 + 1]);
            }
        #pragma unroll
        for (int m = 0; m < 2; m++)
            #pragma unroll
            for (int rr = 0; rr < 2; rr++) {
                const int grow = rowBase + wm * 32 + m * 16 + (lane >> 2) + rr * 8;
                const float tot = rs[m][rr] + xrs[wm * 32 + m * 16 + (lane >> 2) + rr * 8];
                if ((lane & 3) == 0)
                    g_rsP[(size_t)z * (BB * NH * HWP) + (size_t)(b * NH + h) * HWP + grow] = tot;
                __half* od = g_Oph + (size_t)z * (BB * HWP * DM) + (size_t)(b * HWP + grow) * DM + h * DK;
                #pragma unroll
                for (int n = 0; n < 4; n++)
                    *(uint32_t*)(od + n * 8 + c2) = o[m][n][rr];
            }
    }
}

// ---------------------------------------------------------------------------
// Kernel 2b: combine KV-split partials: O = (o0+o1) / (r0+r1).
// ---------------------------------------------------------------------------
__global__ __launch_bounds__(256) void comb_kernel()
{
    const int idx = blockIdx.x * 256 + threadIdx.x;
    const int d    = (idx * 2) & (DM - 1);
    const int pidx = (idx * 2) >> 8;
    const int bb   = pidx / HWP;
    const int p    = pidx - bb * HWP;
    const int hh   = d >> 5;
    const size_t rsi = (size_t)(bb * NH + hh) * HWP + p;
    const float r = g_rsP[rsi] + g_rsP[(size_t)(BB * NH * HWP) + rsi];
    const float inv = __fdividef(1.0f, r);
    const uint32_t o0 = ((const uint32_t*)g_Oph)[idx];
    const uint32_t o1 = ((const uint32_t*)g_Oph)[idx + (BB * HWP * DM) / 2];
    float2 f0 = h2f2(o0), f1 = h2f2(o1);
    ((uint32_t*)g_Oh)[idx] = f2h2((f0.x + f1.x) * inv, (f0.y + f1.y) * inv);
}

// ---------------------------------------------------------------------------
// Kernel 3: HMMA output projection + residual, 64x64 tiles (unchanged).
// ---------------------------------------------------------------------------
__global__ __launch_bounds__(256) void outproj_mma_kernel(
    const float* __restrict__ x, const float* __restrict__ bo,
    const float* __restrict__ gamma_p, float* __restrict__ out)
{
    __shared__ __align__(16) __half ws2[2][64 * QPAD];
    __shared__ __align__(16) __half os2[2][64 * QPAD];

    const int tid  = threadIdx.x;
    const int warp = tid >> 5;
    const int lane = tid & 31;

    const int gp    = blockIdx.x * 64;
    const int b     = gp / HWP;
    const int pb    = gp - b * HWP;
    const int cBase = blockIdx.y * 64;
    const float gamma = *gamma_p;

    const uint32_t wsA = smem_u32(ws2);
    const uint32_t osA = smem_u32(os2);

    auto load_chunk = [&](int s, int k0) {
        const char* wb = (const char*)g_Woh + ((size_t)cBase * DM + k0) * 2;
        const char* ob = (const char*)g_Oh + ((size_t)(b * HWP + pb) * DM + k0) * 2;
        {
            const int i = tid;
            const int r = i >> 2, q = i & 3;
            CPA16(wsA + s * 5120 + r * 80 + q * 16, wb + (size_t)r * (DM * 2) + q * 16);
            CPA16(osA + s * 5120 + r * 80 + q * 16, ob + (size_t)r * (DM * 2) + q * 16);
        }
        CPA_COMMIT();
    };

    const int cw = warp >> 2;
    const int pw = warp & 3;

    float acc[2][2][4] = {};

    load_chunk(0, 0);

    for (int c = 0; c < 8; c++) {
        CPA_WAIT0();
        __syncthreads();
        if (c < 7) load_chunk((c + 1) & 1, (c + 1) * 32);
        const int s = c & 1;

        const int arow = (lane & 7) + ((lane >> 3) & 1) * 8;
        const int acol = (lane >> 4) * 8;
        const int brow = (lane & 7) + ((lane >> 4) & 1) * 8;
        const int bcol = ((lane >> 3) & 1) * 8;

        #pragma unroll
        for (int ks = 0; ks < 2; ks++) {
            uint32_t af[2][4];
            #pragma unroll
            for (int mt = 0; mt < 2; mt++) {
                uint32_t a = smem_u32(&ws2[s][(cw * 32 + mt * 16 + arow) * QPAD + ks * 16 + acol]);
                ldmx4(af[mt][0], af[mt][1], af[mt][2], af[mt][3], a);
            }
            uint32_t bf[4];
            uint32_t a = smem_u32(&os2[s][(pw * 16 + brow) * QPAD + ks * 16 + bcol]);
            ldmx4(bf[0], bf[1], bf[2], bf[3], a);
            #pragma unroll
            for (int mt = 0; mt < 2; mt++) {
                mma16816f(acc[mt][0], af[mt], bf);
                mma16816f(acc[mt][1], af[mt], bf + 2);
            }
        }
    }

    const int c2 = 2 * (lane & 3);
    #pragma unroll
    for (int mt = 0; mt < 2; mt++) {
        #pragma unroll
        for (int rr = 0; rr < 2; rr++) {
            const int c = cBase + cw * 32 + mt * 16 + (lane >> 2) + rr * 8;
            const float bias = bo[c];
            #pragma unroll
            for (int nt = 0; nt < 2; nt++) {
                const int p = pb + pw * 16 + nt * 8 + c2;
                const size_t idx = (size_t)b * CC * HWP + (size_t)c * HWP + p;
                float2 xv = *(const float2*)(x + idx);
                float2 r;
                r.x = xv.x + gamma * acc[mt][nt][rr * 2 + 0] + bias;
                r.y = xv.y + gamma * acc[mt][nt][rr * 2 + 1] + bias;
                *(float2*)(out + idx) = r;
            }
        }
    }
}

// ---------------------------------------------------------------------------
extern "C" void kernel_launch(void* const* d_in, const int* in_sizes, int n_in,
                              void* d_out, int out_size)
{
    (void)in_sizes; (void)n_in; (void)out_size;
    const float* x   = (const float*)d_in[0];
    const float* Wq  = (const float*)d_in[1];
    const float* bq  = (const float*)d_in[2];
    const float* Wk  = (const float*)d_in[3];
    const float* bk  = (const float*)d_in[4];
    const float* Wv  = (const float*)d_in[5];
    const float* bv  = (const float*)d_in[6];
    const float* Wo  = (const float*)d_in[7];
    const float* bo  = (const float*)d_in[8];
    const float* lam = (const float*)d_in[9];
    const float* gam = (const float*)d_in[10];
    float* out = (float*)d_out;

    prep_kernel<<<548, 256>>>(lam, Wq, Wk, Wv, Wo);
    bias_fill_kernel<<<(HWP * HWP / 4) / 256, 256>>>();
    xt_kernel<<<dim3(HWP / 64, CC / 64, BB), 256>>>(x);

    qkv_mma_kernel<<<dim3(BB * HWP / 64, DM / 64), 256>>>(bq, bk, bv);

    attn_mma_kernel<<<dim3(HWP / 128, BB * NH, NSPLIT), 256>>>();
    comb_kernel<<<(BB * HWP * DM / 2) / 256, 256>>>();

    outproj_mma_kernel<<<dim3(BB * HWP / 64, CC / 64), 256>>>(x, bo, gam, out);
}

// round 13
// speedup vs baseline: 1.1303x; 1.1303x over previous
#include <cuda_runtime.h>
#include <cuda_fp16.h>
#include <cstdint>

#define BB 2
#define CC 256
#define HH 48
#define WW 48
#define HWP 2304
#define DM 256
#define NH 8
#define DK 32
#define QK_SCALE 0.17677669529663689f   // 1/sqrt(32)
#define LOG2E 1.4426950408889634f
#define EXP_OFF 7.0f                     // p scaled by 2^-7; cancels in softmax
#define QPAD 40                          // f16 pitch = 80B (16B multiple)
#define WPAD 40
#define BPITCH 80                        // bias tile pitch bytes
#define NSPLIT 2
#define NTILE (HWP / 64)                 // 36
#define TPS (NTILE / NSPLIT)             // 18 tiles per split

// ---------------- scratch (allocation-free) ----------------
__device__ __half g_Qh[BB * HWP * DM];
__device__ __half g_Kh[BB * HWP * DM];
__device__ __half g_Vh[BB * HWP * DM];
__device__ __half g_Oph[NSPLIT * BB * HWP * DM];   // partial attention out
__device__ float  g_rsP[NSPLIT * BB * NH * HWP];   // partial row sums
__device__ __half g_xh[BB * HWP * CC];             // x transposed (b,p,c)
__device__ __half g_Wqh[DM * CC];
__device__ __half g_Wkh[DM * CC];
__device__ __half g_Wvh[DM * CC];
__device__ __half g_Woh[CC * DM];
__device__ unsigned char g_dtab[95 * 95];
__device__ unsigned char g_biasF8[HWP * HWP];

// ---------------- helpers ----------------
__device__ __forceinline__ uint32_t smem_u32(const void* p) {
    uint32_t a;
    asm("{ .reg .u64 t; cvta.to.shared.u64 t, %1; cvt.u32.u64 %0, t; }" : "=r"(a) : "l"(p));
    return a;
}
__device__ __forceinline__ void ldmx4(uint32_t& r0, uint32_t& r1, uint32_t& r2, uint32_t& r3, uint32_t a) {
    asm volatile("ldmatrix.sync.aligned.m8n8.x4.shared.b16 {%0,%1,%2,%3}, [%4];"
                 : "=r"(r0), "=r"(r1), "=r"(r2), "=r"(r3) : "r"(a));
}
__device__ __forceinline__ void ldmx4t(uint32_t& r0, uint32_t& r1, uint32_t& r2, uint32_t& r3, uint32_t a) {
    asm volatile("ldmatrix.sync.aligned.m8n8.x4.trans.shared.b16 {%0,%1,%2,%3}, [%4];"
                 : "=r"(r0), "=r"(r1), "=r"(r2), "=r"(r3) : "r"(a));
}
__device__ __forceinline__ void mma16816f(float* c, const uint32_t* a, const uint32_t* b) {
    asm volatile("mma.sync.aligned.m16n8k16.row.col.f32.f16.f16.f32 "
                 "{%0,%1,%2,%3},{%4,%5,%6,%7},{%8,%9},{%0,%1,%2,%3};"
                 : "+f"(c[0]), "+f"(c[1]), "+f"(c[2]), "+f"(c[3])
                 : "r"(a[0]), "r"(a[1]), "r"(a[2]), "r"(a[3]), "r"(b[0]), "r"(b[1]));
}
__device__ __forceinline__ void mma16816h(uint32_t* d, const uint32_t* a, uint32_t b0, uint32_t b1) {
    asm volatile("mma.sync.aligned.m16n8k16.row.col.f16.f16.f16.f16 "
                 "{%0,%1},{%2,%3,%4,%5},{%6,%7},{%0,%1};"
                 : "+r"(d[0]), "+r"(d[1])
                 : "r"(a[0]), "r"(a[1]), "r"(a[2]), "r"(a[3]), "r"(b0), "r"(b1));
}
__device__ __forceinline__ uint32_t f2h2(float lo, float hi) {
    __half2 h = __floats2half2_rn(lo, hi);
    return *(uint32_t*)&h;
}
__device__ __forceinline__ uint32_t hfma2u(uint32_t a, uint32_t b, uint32_t c) {
    uint32_t d;
    asm("fma.rn.f16x2 %0, %1, %2, %3;" : "=r"(d) : "r"(a), "r"(b), "r"(c));
    return d;
}
__device__ __forceinline__ uint32_t hadd2u(uint32_t a, uint32_t b) {
    uint32_t d;
    asm("add.rn.f16x2 %0, %1, %2;" : "=r"(d) : "r"(a), "r"(b));
    return d;
}
__device__ __forceinline__ uint32_t hmul2u(uint32_t a, uint32_t b) {
    uint32_t d;
    asm("mul.rn.f16x2 %0, %1, %2;" : "=r"(d) : "r"(a), "r"(b));
    return d;
}
__device__ __forceinline__ uint32_t hex2u(uint32_t a) {
    uint32_t d;
    asm("ex2.approx.f16x2 %0, %1;" : "=r"(d) : "r"(a));
    return d;
}
__device__ __forceinline__ float2 h2f2(uint32_t u) {
    __half2 h = *(__half2*)&u;
    return __half22float2(h);
}
#define CPA16(dst, src) asm volatile("cp.async.cg.shared.global [%0], [%1], 16;" :: "r"(dst), "l"(src))
#define CPA_COMMIT()    asm volatile("cp.async.commit_group;")
#define CPA_WAIT0()     asm volatile("cp.async.wait_group 0;")

// ---------------------------------------------------------------------------
// Prep A (merged): blocks [0,512): W fp32->f16; blocks [512,548): dtab.
// ---------------------------------------------------------------------------
__global__ __launch_bounds__(256) void prep_kernel(
    const float* __restrict__ lam_p,
    const float* __restrict__ Wq, const float* __restrict__ Wk,
    const float* __restrict__ Wv, const float* __restrict__ Wo)
{
    const int bx = blockIdx.x;
    if (bx < 512) {
        const int idx = bx * 256 + threadIdx.x;
        const int mat = idx >> 15;
        const int off = idx & 32767;
        const float* s = (mat == 0) ? Wq : ((mat == 1) ? Wk : ((mat == 2) ? Wv : Wo));
        uint32_t* d = (uint32_t*)((mat == 0) ? g_Wqh : ((mat == 1) ? g_Wkh : ((mat == 2) ? g_Wvh : g_Woh)));
        d[off] = f2h2(s[off * 2], s[off * 2 + 1]);
    } else {
        const int idx = (bx - 512) * 256 + threadIdx.x;
        if (idx >= 95 * 95) return;
        const float lam2 = (*lam_p) * LOG2E;
        const int dy = idx / 95 - 47;
        const int dx = idx % 95 - 47;
        const float t = lam2 * __expf(-sqrtf((float)(dy * dy + dx * dx)));
        unsigned short u;
        asm("cvt.rn.satfinite.e4m3x2.f32 %0, %1, %2;" : "=h"(u) : "f"(t), "f"(t));
        g_dtab[idx] = (unsigned char)(u & 0xFF);
    }
}

// ---------------------------------------------------------------------------
// Prep B: expand bias matrix by table lookup.
// ---------------------------------------------------------------------------
__global__ __launch_bounds__(256) void bias_fill_kernel()
{
    const int idx = blockIdx.x * 256 + threadIdx.x;
    const int i  = idx / (HWP / 4);
    const int j0 = (idx - i * (HWP / 4)) * 4;
    const int yi = i / WW, xi = i - yi * WW;
    uint32_t out = 0;
    #pragma unroll
    for (int u = 0; u < 4; u++) {
        const int j  = j0 + u;
        const int yj = j / WW;
        const int xj = j - yj * WW;
        const int ti = (yi - yj + 47) * 95 + (xi - xj + 47);
        out |= (uint32_t)g_dtab[ti] << (u * 8);
    }
    ((uint32_t*)g_biasF8)[idx] = out;
}

// ---------------------------------------------------------------------------
// Prep C: transpose+convert x (b,c,p) fp32 -> g_xh (b,p,c) f16 (vectorized).
// ---------------------------------------------------------------------------
__global__ __launch_bounds__(256) void xt_kernel(const float* __restrict__ x)
{
    __shared__ float ts[64][65];
    const int b  = blockIdx.z;
    const int pB = blockIdx.x * 64;
    const int cB = blockIdx.y * 64;
    #pragma unroll
    for (int i = threadIdx.x; i < 1024; i += 256) {
        const int c  = i >> 4;
        const int pq = (i & 15) * 4;
        const float4 v = *(const float4*)&x[((size_t)b * CC + cB + c) * HWP + pB + pq];
        ts[c][pq + 0] = v.x;
        ts[c][pq + 1] = v.y;
        ts[c][pq + 2] = v.z;
        ts[c][pq + 3] = v.w;
    }
    __syncthreads();
    #pragma unroll
    for (int i = threadIdx.x; i < 1024; i += 256) {
        const int p  = i >> 4;
        const int cq = (i & 15) * 4;
        uint2 o;
        o.x = f2h2(ts[cq + 0][p], ts[cq + 1][p]);
        o.y = f2h2(ts[cq + 2][p], ts[cq + 3][p]);
        *(uint2*)(g_xh + ((size_t)(b * HWP + pB + p) * CC + cB + cq)) = o;
    }
}

// ---------------------------------------------------------------------------
// Kernel 1: HMMA fused QKV + pe + bias, 2-stage cp.async (unchanged from R11).
// ---------------------------------------------------------------------------
__global__ __launch_bounds__(256) void qkv_mma_kernel(
    const float* __restrict__ bq, const float* __restrict__ bk, const float* __restrict__ bv)
{
    __shared__ __align__(16) __half As[2][64 * QPAD];
    __shared__ __align__(16) __half Ws[2][3][64 * WPAD];

    const int tid  = threadIdx.x;
    const int warp = tid >> 5;
    const int lane = tid & 31;

    const int gp    = blockIdx.x * 64;
    const int b     = gp / HWP;
    const int pb    = gp - b * HWP;
    const int dBase = blockIdx.y * 64;
    const bool use_y = (dBase >= 128);

    const uint32_t asA = smem_u32(As);
    const uint32_t wsA = smem_u32(Ws);

    const __half* gW[3] = { g_Wqh, g_Wkh, g_Wvh };

    auto load_chunk = [&](int s, int c0) {
        const char* ab = (const char*)g_xh + ((size_t)(b * HWP + pb) * CC + c0) * 2;
        {
            const int i = tid;
            const int r = i >> 2, q = i & 3;
            CPA16(asA + s * 5120 + r * 80 + q * 16, ab + (size_t)r * (CC * 2) + q * 16);
        }
        #pragma unroll
        for (int i = tid; i < 768; i += 256) {
            const int mat = i / 256;
            const int rem = i - mat * 256;
            const int r = rem >> 2, q = rem & 3;
            const char* wb = (const char*)gW[mat] + ((size_t)(dBase + r) * CC + c0) * 2;
            CPA16(wsA + s * 15360 + mat * 5120 + r * 80 + q * 16, wb + q * 16);
        }
        CPA_COMMIT();
    };

    const int mw = warp >> 2;
    const int nw = warp & 3;

    float acc[3][2][2][4] = {};

    load_chunk(0, 0);

    for (int c = 0; c < 8; c++) {
        CPA_WAIT0();
        __syncthreads();
        if (c < 7) load_chunk((c + 1) & 1, (c + 1) * 32);

        const int s = c & 1;
        const __half* Ab = As[s];

        const int arow = (lane & 7) + ((lane >> 3) & 1) * 8;
        const int acol = (lane >> 4) * 8;
        const int brow = (lane & 7) + ((lane >> 4) & 1) * 8;
        const int bcol = ((lane >> 3) & 1) * 8;

        #pragma unroll
        for (int ks = 0; ks < 2; ks++) {
            uint32_t af[2][4];
            #pragma unroll
            for (int mt = 0; mt < 2; mt++) {
                uint32_t a = smem_u32(Ab + (mw * 32 + mt * 16 + arow) * QPAD + ks * 16 + acol);
                ldmx4(af[mt][0], af[mt][1], af[mt][2], af[mt][3], a);
            }
            #pragma unroll
            for (int mat = 0; mat < 3; mat++) {
                uint32_t bf[4];
                uint32_t a = smem_u32(&Ws[s][mat][(nw * 16 + brow) * WPAD + ks * 16 + bcol]);
                ldmx4(bf[0], bf[1], bf[2], bf[3], a);
                #pragma unroll
                for (int mt = 0; mt < 2; mt++) {
                    mma16816f(acc[mat][mt][0], af[mt], bf);
                    mma16816f(acc[mat][mt][1], af[mt], bf + 2);
                }
            }
        }
    }

    __syncthreads();
    __half* pes = (__half*)As;
    for (int i = tid; i < 48 * 64; i += 256) {
        const int coord = i >> 6;
        const int dloc  = i & 63;
        const int dl    = (dBase + dloc) - (use_y ? 128 : 0);
        const float freq = __expf(-(float)(dl >> 1) * 0.14391156642875743f);
        const float arg  = (float)coord * freq;
        pes[i] = __float2half((dl & 1) ? __cosf(arg) : __sinf(arg));
    }
    __syncthreads();

    const int c2 = 2 * (lane & 3);
    #pragma unroll
    for (int mt = 0; mt < 2; mt++) {
        #pragma unroll
        for (int rr = 0; rr < 2; rr++) {
            const int ploc = mw * 32 + mt * 16 + (lane >> 2) + rr * 8;
            const int p    = pb + ploc;
            const int coord = use_y ? (p / WW) : (p % WW);
            const size_t rowIdx = ((size_t)b * HWP + p) * DM + dBase;
            #pragma unroll
            for (int nt = 0; nt < 2; nt++) {
                const int dloc = nw * 16 + nt * 8 + c2;
                const int d    = dBase + dloc;
                const float pe0 = __half2float(pes[coord * 64 + dloc]);
                const float pe1 = __half2float(pes[coord * 64 + dloc + 1]);
                const float q0 = acc[0][mt][nt][rr * 2 + 0] + bq[d]     + pe0;
                const float q1 = acc[0][mt][nt][rr * 2 + 1] + bq[d + 1] + pe1;
                const float k0 = acc[1][mt][nt][rr * 2 + 0] + bk[d]     + pe0;
                const float k1 = acc[1][mt][nt][rr * 2 + 1] + bk[d + 1] + pe1;
                const float v0 = acc[2][mt][nt][rr * 2 + 0] + bv[d];
                const float v1 = acc[2][mt][nt][rr * 2 + 1] + bv[d + 1];
                *(uint32_t*)(g_Qh + rowIdx + dloc) = f2h2(q0, q1);
                *(uint32_t*)(g_Kh + rowIdx + dloc) = f2h2(k0, k1);
                *(uint32_t*)(g_Vh + rowIdx + dloc) = f2h2(v0, v1);
            }
        }
    }
}

// ---------------------------------------------------------------------------
// Kernel 2: f16 HMMA flash attention, KV-split (exact R11 form: 128 thr).
// ---------------------------------------------------------------------------
__global__ __launch_bounds__(128, 4) void attn_mma_kernel()
{
    __shared__ __align__(16) __half Qs[128 * QPAD];
    __shared__ __align__(16) __half Ks[2][64 * QPAD];
    __shared__ __align__(16) __half Vs[2][64 * QPAD];
    __shared__ __align__(16) unsigned char Bs[2][128 * BPITCH];

    const int tid  = threadIdx.x;
    const int warp = tid >> 5;
    const int lane = tid & 31;
    const int b    = blockIdx.y >> 3;
    const int h    = blockIdx.y & 7;
    const int rowBase = blockIdx.x * 128;
    const int z    = blockIdx.z;
    const int tBeg = z * TPS;

    const uint32_t ksA = smem_u32(Ks);
    const uint32_t vsA = smem_u32(Vs);
    const uint32_t bsA = smem_u32(Bs);

    auto issue_tile = [&](int t, int s) {
        const int jt = t * 64;
        const char* kb = (const char*)g_Kh + ((size_t)(b * HWP + jt) * DM + h * DK) * 2;
        const char* vb = (const char*)g_Vh + ((size_t)(b * HWP + jt) * DM + h * DK) * 2;
        #pragma unroll
        for (int i = tid; i < 256; i += 128) {
            const int r = i >> 2, q = i & 3;
            CPA16(ksA + s * 5120 + r * 80 + q * 16, kb + (size_t)r * (DM * 2) + q * 16);
            CPA16(vsA + s * 5120 + r * 80 + q * 16, vb + (size_t)r * (DM * 2) + q * 16);
        }
        const unsigned char* bb = g_biasF8 + (size_t)rowBase * HWP + jt;
        #pragma unroll
        for (int i = tid; i < 512; i += 128) {
            const int r = i >> 2, q = i & 3;
            CPA16(bsA + s * 10240 + r * BPITCH + q * 16, bb + (size_t)r * HWP + q * 16);
        }
        CPA_COMMIT();
    };

    {
        const __half* qsrc = g_Qh + (size_t)(b * HWP + rowBase) * DM + h * DK;
        #pragma unroll
        for (int i = tid; i < 512; i += 128) {
            const int r = i >> 2, q = i & 3;
            *(uint4*)(Qs + r * QPAD + q * 8) = *(const uint4*)(qsrc + (size_t)r * DM + q * 8);
        }
    }
    issue_tile(tBeg, 0);
    __syncthreads();

    uint32_t qa[2][2][4];
    {
        const int arow = (lane & 7) + ((lane >> 3) & 1) * 8;
        const int acol = (lane >> 4) * 8;
        #pragma unroll
        for (int m = 0; m < 2; m++)
            #pragma unroll
            for (int ks = 0; ks < 2; ks++) {
                uint32_t a = smem_u32(Qs + (warp * 32 + m * 16 + arow) * QPAD + ks * 16 + acol);
                ldmx4(qa[m][ks][0], qa[m][ks][1], qa[m][ks][2], qa[m][ks][3], a);
            }
    }

    const int c2 = 2 * (lane & 3);
    int boff[2][2];
    #pragma unroll
    for (int m = 0; m < 2; m++)
        #pragma unroll
        for (int rr = 0; rr < 2; rr++)
            boff[m][rr] = (warp * 32 + m * 16 + (lane >> 2) + rr * 8) * BPITCH + c2;

    const uint32_t SC2h = f2h2(QK_SCALE * LOG2E, QK_SCALE * LOG2E);
    const uint32_t NEGO = f2h2(-EXP_OFF, -EXP_OFF);

    uint32_t o[2][4][2];
    uint32_t rsum2[2][2];
    #pragma unroll
    for (int m = 0; m < 2; m++) {
        #pragma unroll
        for (int n = 0; n < 4; n++) { o[m][n][0] = 0u; o[m][n][1] = 0u; }
        rsum2[m][0] = 0u; rsum2[m][1] = 0u;
    }

    for (int t = 0; t < TPS; t++) {
        CPA_WAIT0();
        __syncthreads();
        if (t < TPS - 1) issue_tile(tBeg + t + 1, (t + 1) & 1);
        const int s = t & 1;

        uint32_t S[2][8][2];
        #pragma unroll
        for (int m = 0; m < 2; m++)
            #pragma unroll
            for (int n = 0; n < 8; n++) { S[m][n][0] = 0u; S[m][n][1] = 0u; }
        {
            const int brow = (lane & 7) + ((lane >> 4) & 1) * 8;
            const int bcol = ((lane >> 3) & 1) * 8;
            #pragma unroll
            for (int np = 0; np < 4; np++) {
                #pragma unroll
                for (int ks = 0; ks < 2; ks++) {
                    uint32_t kf[4];
                    uint32_t a = smem_u32(&Ks[s][(np * 16 + brow) * QPAD + ks * 16 + bcol]);
                    ldmx4(kf[0], kf[1], kf[2], kf[3], a);
                    #pragma unroll
                    for (int m = 0; m < 2; m++) {
                        mma16816h(S[m][2 * np],     qa[m][ks], kf[0], kf[1]);
                        mma16816h(S[m][2 * np + 1], qa[m][ks], kf[2], kf[3]);
                    }
                }
            }
        }

        const unsigned char* bbuf = Bs[s];
        #pragma unroll
        for (int n = 0; n < 8; n++) {
            #pragma unroll
            for (int m = 0; m < 2; m++) {
                const unsigned short h0 = *(const unsigned short*)(bbuf + boff[m][0] + n * 8);
                const unsigned short h1 = *(const unsigned short*)(bbuf + boff[m][1] + n * 8);
                uint32_t b0, b1;
                asm("cvt.rn.f16x2.e4m3x2 %0, %1;" : "=r"(b0) : "h"(h0));
                asm("cvt.rn.f16x2.e4m3x2 %0, %1;" : "=r"(b1) : "h"(h1));
                b0 = hadd2u(b0, NEGO);
                b1 = hadd2u(b1, NEGO);
                S[m][n][0] = hex2u(hfma2u(S[m][n][0], SC2h, b0));
                S[m][n][1] = hex2u(hfma2u(S[m][n][1], SC2h, b1));
                rsum2[m][0] = hadd2u(rsum2[m][0], S[m][n][0]);
                rsum2[m][1] = hadd2u(rsum2[m][1], S[m][n][1]);
            }
        }

        {
            const int vrow = (lane & 7) + ((lane >> 3) & 1) * 8;
            const int vcol = ((lane >> 4) & 1) * 8;
            #pragma unroll
            for (int k2 = 0; k2 < 4; k2++) {
                #pragma unroll
                for (int dp = 0; dp < 2; dp++) {
                    uint32_t vf[4];
                    uint32_t a = smem_u32(&Vs[s][(k2 * 16 + vrow) * QPAD + dp * 16 + vcol]);
                    ldmx4t(vf[0], vf[1], vf[2], vf[3], a);
                    #pragma unroll
                    for (int m = 0; m < 2; m++) {
                        mma16816h(o[m][2 * dp],     &S[m][2 * k2][0], vf[0], vf[1]);
                        mma16816h(o[m][2 * dp + 1], &S[m][2 * k2][0], vf[2], vf[3]);
                    }
                }
            }
        }
    }

    #pragma unroll
    for (int m = 0; m < 2; m++)
        #pragma unroll
        for (int rr = 0; rr < 2; rr++) {
            float2 f = h2f2(rsum2[m][rr]);
            float sv = f.x + f.y;
            sv += __shfl_xor_sync(0xFFFFFFFF, sv, 1);
            sv += __shfl_xor_sync(0xFFFFFFFF, sv, 2);
            if ((lane & 3) == 0) {
                const int grow = rowBase + warp * 32 + m * 16 + (lane >> 2) + rr * 8;
                g_rsP[(size_t)z * (BB * NH * HWP) + (size_t)(b * NH + h) * HWP + grow] = sv;
            }
        }

    #pragma unroll
    for (int m = 0; m < 2; m++)
        #pragma unroll
        for (int rr = 0; rr < 2; rr++) {
            const int grow = rowBase + warp * 32 + m * 16 + (lane >> 2) + rr * 8;
            __half* od = g_Oph + (size_t)z * (BB * HWP * DM) + (size_t)(b * HWP + grow) * DM + h * DK;
            #pragma unroll
            for (int n = 0; n < 4; n++)
                *(uint32_t*)(od + n * 8 + c2) = o[m][n][rr];
        }
}

// ---------------------------------------------------------------------------
// Kernel 3: HMMA output projection + residual, with fused KV-split combine.
// O staging: register-loads both Oph halves + row sums, combines into smem.
// W staging: cp.async double-buffered. CTA 256: M=64 c x N=64 p. Grid (72,4).
// ---------------------------------------------------------------------------
__global__ __launch_bounds__(256) void outproj_mma_kernel(
    const float* __restrict__ x, const float* __restrict__ bo,
    const float* __restrict__ gamma_p, float* __restrict__ out)
{
    __shared__ __align__(16) __half ws2[2][64 * QPAD];
    __shared__ __align__(16) __half os2[2][64 * QPAD];

    const int tid  = threadIdx.x;
    const int warp = tid >> 5;
    const int lane = tid & 31;

    const int gp    = blockIdx.x * 64;
    const int b     = gp / HWP;
    const int pb    = gp - b * HWP;
    const int cBase = blockIdx.y * 64;
    const float gamma = *gamma_p;

    const uint32_t wsA = smem_u32(ws2);

    auto load_w = [&](int s, int k0) {
        const char* wb = (const char*)g_Woh + ((size_t)cBase * DM + k0) * 2;
        const int r = tid >> 2, q = tid & 3;
        CPA16(wsA + s * 5120 + r * 80 + q * 16, wb + (size_t)r * (DM * 2) + q * 16);
        CPA_COMMIT();
    };

    // O register staging: thread handles row r = tid>>2, 8 dims at q*8.
    const int orow = tid >> 2;
    const int oq   = tid & 3;
    auto load_o = [&](int k0, uint4& a0, uint4& a1, float& inv) {
        const int hh = k0 >> 5;
        const size_t base = (size_t)(b * HWP + pb + orow) * DM + k0 + oq * 8;
        a0 = *(const uint4*)(g_Oph + base);
        a1 = *(const uint4*)(g_Oph + (size_t)(BB * HWP * DM) + base);
        const size_t rsi = (size_t)(b * NH + hh) * HWP + pb + orow;
        inv = __fdividef(1.0f, g_rsP[rsi] + g_rsP[(size_t)(BB * NH * HWP) + rsi]);
    };
    auto store_o = [&](int s, uint4 a0, uint4 a1, float inv) {
        const uint32_t iv = f2h2(inv, inv);
        uint4 r;
        r.x = hmul2u(hadd2u(a0.x, a1.x), iv);
        r.y = hmul2u(hadd2u(a0.y, a1.y), iv);
        r.z = hmul2u(hadd2u(a0.z, a1.z), iv);
        r.w = hmul2u(hadd2u(a0.w, a1.w), iv);
        *(uint4*)(&os2[s][orow * QPAD + oq * 8]) = r;
    };

    const int cw = warp >> 2;
    const int pw = warp & 3;

    float acc[2][2][4] = {};

    load_w(0, 0);
    uint4 oa0, oa1;
    float oinv;
    load_o(0, oa0, oa1, oinv);

    for (int c = 0; c < 8; c++) {
        CPA_WAIT0();
        __syncthreads();
        const int s = c & 1;
        store_o(s, oa0, oa1, oinv);
        if (c < 7) {
            load_w((c + 1) & 1, (c + 1) * 32);
            load_o((c + 1) * 32, oa0, oa1, oinv);
        }
        __syncthreads();

        const int arow = (lane & 7) + ((lane >> 3) & 1) * 8;
        const int acol = (lane >> 4) * 8;
        const int brow = (lane & 7) + ((lane >> 4) & 1) * 8;
        const int bcol = ((lane >> 3) & 1) * 8;

        #pragma unroll
        for (int ks = 0; ks < 2; ks++) {
            uint32_t af[2][4];
            #pragma unroll
            for (int mt = 0; mt < 2; mt++) {
                uint32_t a = smem_u32(&ws2[s][(cw * 32 + mt * 16 + arow) * QPAD + ks * 16 + acol]);
                ldmx4(af[mt][0], af[mt][1], af[mt][2], af[mt][3], a);
            }
            uint32_t bf[4];
            uint32_t a = smem_u32(&os2[s][(pw * 16 + brow) * QPAD + ks * 16 + bcol]);
            ldmx4(bf[0], bf[1], bf[2], bf[3], a);
            #pragma unroll
            for (int mt = 0; mt < 2; mt++) {
                mma16816f(acc[mt][0], af[mt], bf);
                mma16816f(acc[mt][1], af[mt], bf + 2);
            }
        }
    }

    const int c2 = 2 * (lane & 3);
    #pragma unroll
    for (int mt = 0; mt < 2; mt++) {
        #pragma unroll
        for (int rr = 0; rr < 2; rr++) {
            const int c = cBase + cw * 32 + mt * 16 + (lane >> 2) + rr * 8;
            const float bias = bo[c];
            #pragma unroll
            for (int nt = 0; nt < 2; nt++) {
                const int p = pb + pw * 16 + nt * 8 + c2;
                const size_t idx = (size_t)b * CC * HWP + (size_t)c * HWP + p;
                float2 xv = *(const float2*)(x + idx);
                float2 r;
                r.x = xv.x + gamma * acc[mt][nt][rr * 2 + 0] + bias;
                r.y = xv.y + gamma * acc[mt][nt][rr * 2 + 1] + bias;
                *(float2*)(out + idx) = r;
            }
        }
    }
}

// ---------------------------------------------------------------------------
extern "C" void kernel_launch(void* const* d_in, const int* in_sizes, int n_in,
                              void* d_out, int out_size)
{
    (void)in_sizes; (void)n_in; (void)out_size;
    const float* x   = (const float*)d_in[0];
    const float* Wq  = (const float*)d_in[1];
    const float* bq  = (const float*)d_in[2];
    const float* Wk  = (const float*)d_in[3];
    const float* bk  = (const float*)d_in[4];
    const float* Wv  = (const float*)d_in[5];
    const float* bv  = (const float*)d_in[6];
    const float* Wo  = (const float*)d_in[7];
    const float* bo  = (const float*)d_in[8];
    const float* lam = (const float*)d_in[9];
    const float* gam = (const float*)d_in[10];
    float* out = (float*)d_out;

    prep_kernel<<<548, 256>>>(lam, Wq, Wk, Wv, Wo);
    bias_fill_kernel<<<(HWP * HWP / 4) / 256, 256>>>();
    xt_kernel<<<dim3(HWP / 64, CC / 64, BB), 256>>>(x);

    qkv_mma_kernel<<<dim3(BB * HWP / 64, DM / 64), 256>>>(bq, bk, bv);

    attn_mma_kernel<<<dim3(HWP / 128, BB * NH, NSPLIT), 128>>>();

    outproj_mma_kernel<<<dim3(BB * HWP / 64, CC / 64), 256>>>(x, bo, gam, out);
}

// round 14
// speedup vs baseline: 1.1717x; 1.0366x over previous
#include <cuda_runtime.h>
#include <cuda_fp16.h>
#include <cstdint>

#define BB 2
#define CC 256
#define HH 48
#define WW 48
#define HWP 2304
#define DM 256
#define NH 8
#define DK 32
#define QK_SCALE 0.17677669529663689f   // 1/sqrt(32)
#define LOG2E 1.4426950408889634f
#define QSC (QK_SCALE * LOG2E)           // folded into Q at projection time
#define EXP_OFF 7.0f                     // folded into bias table; cancels in softmax
#define QPAD 40                          // f16 pitch = 80B (16B multiple)
#define WPAD 40
#define NSPLIT 2
#define NTILE (HWP / 64)                 // 36
#define TPS (NTILE / NSPLIT)             // 18 tiles per split

// ---------------- scratch (allocation-free) ----------------
__device__ __half g_Qh[BB * HWP * DM];
__device__ __half g_Kh[BB * HWP * DM];
__device__ __half g_Vh[BB * HWP * DM];
__device__ __half g_Oph[NSPLIT * BB * HWP * DM];   // partial attention out
__device__ float  g_rsP[NSPLIT * BB * NH * HWP];   // partial row sums
__device__ __half g_xh[BB * HWP * CC];             // x transposed (b,p,c)
__device__ __half g_Wqh[DM * CC];
__device__ __half g_Wkh[DM * CC];
__device__ __half g_Wvh[DM * CC];
__device__ __half g_Woh[CC * DM];
__device__ __half g_dtabH[95 * 95];                // f16: lam*exp(-d)*log2e - 7
__device__ __half g_biasH[HWP * HWP];              // fragment-ordered bias (f16)

// ---------------- helpers ----------------
__device__ __forceinline__ uint32_t smem_u32(const void* p) {
    uint32_t a;
    asm("{ .reg .u64 t; cvta.to.shared.u64 t, %1; cvt.u32.u64 %0, t; }" : "=r"(a) : "l"(p));
    return a;
}
__device__ __forceinline__ void ldmx4(uint32_t& r0, uint32_t& r1, uint32_t& r2, uint32_t& r3, uint32_t a) {
    asm volatile("ldmatrix.sync.aligned.m8n8.x4.shared.b16 {%0,%1,%2,%3}, [%4];"
                 : "=r"(r0), "=r"(r1), "=r"(r2), "=r"(r3) : "r"(a));
}
__device__ __forceinline__ void ldmx4t(uint32_t& r0, uint32_t& r1, uint32_t& r2, uint32_t& r3, uint32_t a) {
    asm volatile("ldmatrix.sync.aligned.m8n8.x4.trans.shared.b16 {%0,%1,%2,%3}, [%4];"
                 : "=r"(r0), "=r"(r1), "=r"(r2), "=r"(r3) : "r"(a));
}
__device__ __forceinline__ void mma16816f(float* c, const uint32_t* a, const uint32_t* b) {
    asm volatile("mma.sync.aligned.m16n8k16.row.col.f32.f16.f16.f32 "
                 "{%0,%1,%2,%3},{%4,%5,%6,%7},{%8,%9},{%0,%1,%2,%3};"
                 : "+f"(c[0]), "+f"(c[1]), "+f"(c[2]), "+f"(c[3])
                 : "r"(a[0]), "r"(a[1]), "r"(a[2]), "r"(a[3]), "r"(b[0]), "r"(b[1]));
}
__device__ __forceinline__ void mma16816h(uint32_t* d, const uint32_t* a, uint32_t b0, uint32_t b1) {
    asm volatile("mma.sync.aligned.m16n8k16.row.col.f16.f16.f16.f16 "
                 "{%0,%1},{%2,%3,%4,%5},{%6,%7},{%0,%1};"
                 : "+r"(d[0]), "+r"(d[1])
                 : "r"(a[0]), "r"(a[1]), "r"(a[2]), "r"(a[3]), "r"(b0), "r"(b1));
}
__device__ __forceinline__ uint32_t f2h2(float lo, float hi) {
    __half2 h = __floats2half2_rn(lo, hi);
    return *(uint32_t*)&h;
}
__device__ __forceinline__ uint32_t hadd2u(uint32_t a, uint32_t b) {
    uint32_t d;
    asm("add.rn.f16x2 %0, %1, %2;" : "=r"(d) : "r"(a), "r"(b));
    return d;
}
__device__ __forceinline__ uint32_t hmul2u(uint32_t a, uint32_t b) {
    uint32_t d;
    asm("mul.rn.f16x2 %0, %1, %2;" : "=r"(d) : "r"(a), "r"(b));
    return d;
}
__device__ __forceinline__ uint32_t hex2u(uint32_t a) {
    uint32_t d;
    asm("ex2.approx.f16x2 %0, %1;" : "=r"(d) : "r"(a));
    return d;
}
__device__ __forceinline__ float2 h2f2(uint32_t u) {
    __half2 h = *(__half2*)&u;
    return __half22float2(h);
}
#define CPA16(dst, src) asm volatile("cp.async.cg.shared.global [%0], [%1], 16;" :: "r"(dst), "l"(src))
#define CPA_COMMIT()    asm volatile("cp.async.commit_group;")
#define CPA_WAIT0()     asm volatile("cp.async.wait_group 0;")

// ---------------------------------------------------------------------------
// Prep A (merged): blocks [0,512): W fp32->f16; blocks [512,548): dtab (f16,
// with -EXP_OFF folded).
// ---------------------------------------------------------------------------
__global__ __launch_bounds__(256) void prep_kernel(
    const float* __restrict__ lam_p,
    const float* __restrict__ Wq, const float* __restrict__ Wk,
    const float* __restrict__ Wv, const float* __restrict__ Wo)
{
    const int bx = blockIdx.x;
    if (bx < 512) {
        const int idx = bx * 256 + threadIdx.x;
        const int mat = idx >> 15;
        const int off = idx & 32767;
        const float* s = (mat == 0) ? Wq : ((mat == 1) ? Wk : ((mat == 2) ? Wv : Wo));
        uint32_t* d = (uint32_t*)((mat == 0) ? g_Wqh : ((mat == 1) ? g_Wkh : ((mat == 2) ? g_Wvh : g_Woh)));
        d[off] = f2h2(s[off * 2], s[off * 2 + 1]);
    } else {
        const int idx = (bx - 512) * 256 + threadIdx.x;
        if (idx >= 95 * 95) return;
        const float lam2 = (*lam_p) * LOG2E;
        const int dy = idx / 95 - 47;
        const int dx = idx % 95 - 47;
        const float t = lam2 * __expf(-sqrtf((float)(dy * dy + dx * dx))) - EXP_OFF;
        g_dtabH[idx] = __float2half(t);
    }
}

// ---------------------------------------------------------------------------
// Prep B: expand bias matrix in MMA-fragment order.
// u32 idx decodes (blk, warp, m, n, rr, lane); blk = R*36 + T.
// ---------------------------------------------------------------------------
__global__ __launch_bounds__(256) void bias_fill_kernel()
{
    const int idx = blockIdx.x * 256 + threadIdx.x;   // HWP*HWP/2 u32s
    const int blk  = idx >> 11;
    const int rem  = idx & 2047;
    const int w    = rem >> 9;
    const int rem2 = rem & 511;
    const int mn   = rem2 >> 6;
    const int rr   = (rem2 >> 5) & 1;
    const int lane = rem2 & 31;
    const int m = mn >> 3, n = mn & 7;
    const int R = blk / 36, T = blk - R * 36;
    const int i = R * 128 + w * 32 + m * 16 + (lane >> 2) + rr * 8;
    const int j = T * 64 + n * 8 + 2 * (lane & 3);
    const int yi = i / WW, xi = i - yi * WW;
    const int yj0 = j / WW,      xj0 = j - yj0 * WW;
    const int yj1 = (j + 1) / WW, xj1 = (j + 1) - yj1 * WW;
    const unsigned short h0 = *(const unsigned short*)&g_dtabH[(yi - yj0 + 47) * 95 + (xi - xj0 + 47)];
    const unsigned short h1 = *(const unsigned short*)&g_dtabH[(yi - yj1 + 47) * 95 + (xi - xj1 + 47)];
    ((uint32_t*)g_biasH)[idx] = (uint32_t)h0 | ((uint32_t)h1 << 16);
}

// ---------------------------------------------------------------------------
// Prep C: transpose+convert x (b,c,p) fp32 -> g_xh (b,p,c) f16 (vectorized).
// ---------------------------------------------------------------------------
__global__ __launch_bounds__(256) void xt_kernel(const float* __restrict__ x)
{
    __shared__ float ts[64][65];
    const int b  = blockIdx.z;
    const int pB = blockIdx.x * 64;
    const int cB = blockIdx.y * 64;
    #pragma unroll
    for (int i = threadIdx.x; i < 1024; i += 256) {
        const int c  = i >> 4;
        const int pq = (i & 15) * 4;
        const float4 v = *(const float4*)&x[((size_t)b * CC + cB + c) * HWP + pB + pq];
        ts[c][pq + 0] = v.x;
        ts[c][pq + 1] = v.y;
        ts[c][pq + 2] = v.z;
        ts[c][pq + 3] = v.w;
    }
    __syncthreads();
    #pragma unroll
    for (int i = threadIdx.x; i < 1024; i += 256) {
        const int p  = i >> 4;
        const int cq = (i & 15) * 4;
        uint2 o;
        o.x = f2h2(ts[cq + 0][p], ts[cq + 1][p]);
        o.y = f2h2(ts[cq + 2][p], ts[cq + 3][p]);
        *(uint2*)(g_xh + ((size_t)(b * HWP + pB + p) * CC + cB + cq)) = o;
    }
}

// ---------------------------------------------------------------------------
// Kernel 1: HMMA fused QKV + pe + bias; Q pre-scaled by QSC.
// ---------------------------------------------------------------------------
__global__ __launch_bounds__(256) void qkv_mma_kernel(
    const float* __restrict__ bq, const float* __restrict__ bk, const float* __restrict__ bv)
{
    __shared__ __align__(16) __half As[2][64 * QPAD];
    __shared__ __align__(16) __half Ws[2][3][64 * WPAD];

    const int tid  = threadIdx.x;
    const int warp = tid >> 5;
    const int lane = tid & 31;

    const int gp    = blockIdx.x * 64;
    const int b     = gp / HWP;
    const int pb    = gp - b * HWP;
    const int dBase = blockIdx.y * 64;
    const bool use_y = (dBase >= 128);

    const uint32_t asA = smem_u32(As);
    const uint32_t wsA = smem_u32(Ws);

    const __half* gW[3] = { g_Wqh, g_Wkh, g_Wvh };

    auto load_chunk = [&](int s, int c0) {
        const char* ab = (const char*)g_xh + ((size_t)(b * HWP + pb) * CC + c0) * 2;
        {
            const int i = tid;
            const int r = i >> 2, q = i & 3;
            CPA16(asA + s * 5120 + r * 80 + q * 16, ab + (size_t)r * (CC * 2) + q * 16);
        }
        #pragma unroll
        for (int i = tid; i < 768; i += 256) {
            const int mat = i / 256;
            const int rem = i - mat * 256;
            const int r = rem >> 2, q = rem & 3;
            const char* wb = (const char*)gW[mat] + ((size_t)(dBase + r) * CC + c0) * 2;
            CPA16(wsA + s * 15360 + mat * 5120 + r * 80 + q * 16, wb + q * 16);
        }
        CPA_COMMIT();
    };

    const int mw = warp >> 2;
    const int nw = warp & 3;

    float acc[3][2][2][4] = {};

    load_chunk(0, 0);

    for (int c = 0; c < 8; c++) {
        CPA_WAIT0();
        __syncthreads();
        if (c < 7) load_chunk((c + 1) & 1, (c + 1) * 32);

        const int s = c & 1;
        const __half* Ab = As[s];

        const int arow = (lane & 7) + ((lane >> 3) & 1) * 8;
        const int acol = (lane >> 4) * 8;
        const int brow = (lane & 7) + ((lane >> 4) & 1) * 8;
        const int bcol = ((lane >> 3) & 1) * 8;

        #pragma unroll
        for (int ks = 0; ks < 2; ks++) {
            uint32_t af[2][4];
            #pragma unroll
            for (int mt = 0; mt < 2; mt++) {
                uint32_t a = smem_u32(Ab + (mw * 32 + mt * 16 + arow) * QPAD + ks * 16 + acol);
                ldmx4(af[mt][0], af[mt][1], af[mt][2], af[mt][3], a);
            }
            #pragma unroll
            for (int mat = 0; mat < 3; mat++) {
                uint32_t bf[4];
                uint32_t a = smem_u32(&Ws[s][mat][(nw * 16 + brow) * WPAD + ks * 16 + bcol]);
                ldmx4(bf[0], bf[1], bf[2], bf[3], a);
                #pragma unroll
                for (int mt = 0; mt < 2; mt++) {
                    mma16816f(acc[mat][mt][0], af[mt], bf);
                    mma16816f(acc[mat][mt][1], af[mt], bf + 2);
                }
            }
        }
    }

    __syncthreads();
    __half* pes = (__half*)As;
    for (int i = tid; i < 48 * 64; i += 256) {
        const int coord = i >> 6;
        const int dloc  = i & 63;
        const int dl    = (dBase + dloc) - (use_y ? 128 : 0);
        const float freq = __expf(-(float)(dl >> 1) * 0.14391156642875743f);
        const float arg  = (float)coord * freq;
        pes[i] = __float2half((dl & 1) ? __cosf(arg) : __sinf(arg));
    }
    __syncthreads();

    const int c2 = 2 * (lane & 3);
    #pragma unroll
    for (int mt = 0; mt < 2; mt++) {
        #pragma unroll
        for (int rr = 0; rr < 2; rr++) {
            const int ploc = mw * 32 + mt * 16 + (lane >> 2) + rr * 8;
            const int p    = pb + ploc;
            const int coord = use_y ? (p / WW) : (p % WW);
            const size_t rowIdx = ((size_t)b * HWP + p) * DM + dBase;
            #pragma unroll
            for (int nt = 0; nt < 2; nt++) {
                const int dloc = nw * 16 + nt * 8 + c2;
                const int d    = dBase + dloc;
                const float pe0 = __half2float(pes[coord * 64 + dloc]);
                const float pe1 = __half2float(pes[coord * 64 + dloc + 1]);
                const float q0 = (acc[0][mt][nt][rr * 2 + 0] + bq[d]     + pe0) * QSC;
                const float q1 = (acc[0][mt][nt][rr * 2 + 1] + bq[d + 1] + pe1) * QSC;
                const float k0 = acc[1][mt][nt][rr * 2 + 0] + bk[d]     + pe0;
                const float k1 = acc[1][mt][nt][rr * 2 + 1] + bk[d + 1] + pe1;
                const float v0 = acc[2][mt][nt][rr * 2 + 0] + bv[d];
                const float v1 = acc[2][mt][nt][rr * 2 + 1] + bv[d + 1];
                *(uint32_t*)(g_Qh + rowIdx + dloc) = f2h2(q0, q1);
                *(uint32_t*)(g_Kh + rowIdx + dloc) = f2h2(k0, k1);
                *(uint32_t*)(g_Vh + rowIdx + dloc) = f2h2(v0, v1);
            }
        }
    }
}

// ---------------------------------------------------------------------------
// Kernel 2: f16 HMMA flash attention, KV-split. Bias loaded via LDG directly
// into the S accumulators (MMA C-init). CTA 128 thr. Grid (18, 16, NSPLIT).
// ---------------------------------------------------------------------------
__global__ __launch_bounds__(128, 4) void attn_mma_kernel()
{
    __shared__ __align__(16) __half Qs[128 * QPAD];
    __shared__ __align__(16) __half Ks[2][64 * QPAD];
    __shared__ __align__(16) __half Vs[2][64 * QPAD];

    const int tid  = threadIdx.x;
    const int warp = tid >> 5;
    const int lane = tid & 31;
    const int b    = blockIdx.y >> 3;
    const int h    = blockIdx.y & 7;
    const int rowBase = blockIdx.x * 128;
    const int z    = blockIdx.z;
    const int tBeg = z * TPS;

    const uint32_t ksA = smem_u32(Ks);
    const uint32_t vsA = smem_u32(Vs);

    auto issue_tile = [&](int t, int s) {
        const int jt = t * 64;
        const char* kb = (const char*)g_Kh + ((size_t)(b * HWP + jt) * DM + h * DK) * 2;
        const char* vb = (const char*)g_Vh + ((size_t)(b * HWP + jt) * DM + h * DK) * 2;
        #pragma unroll
        for (int i = tid; i < 256; i += 128) {
            const int r = i >> 2, q = i & 3;
            CPA16(ksA + s * 5120 + r * 80 + q * 16, kb + (size_t)r * (DM * 2) + q * 16);
            CPA16(vsA + s * 5120 + r * 80 + q * 16, vb + (size_t)r * (DM * 2) + q * 16);
        }
        CPA_COMMIT();
    };

    {
        const __half* qsrc = g_Qh + (size_t)(b * HWP + rowBase) * DM + h * DK;
        #pragma unroll
        for (int i = tid; i < 512; i += 128) {
            const int r = i >> 2, q = i & 3;
            *(uint4*)(Qs + r * QPAD + q * 8) = *(const uint4*)(qsrc + (size_t)r * DM + q * 8);
        }
    }
    issue_tile(tBeg, 0);
    __syncthreads();

    uint32_t qa[2][2][4];
    {
        const int arow = (lane & 7) + ((lane >> 3) & 1) * 8;
        const int acol = (lane >> 4) * 8;
        #pragma unroll
        for (int m = 0; m < 2; m++)
            #pragma unroll
            for (int ks = 0; ks < 2; ks++) {
                uint32_t a = smem_u32(Qs + (warp * 32 + m * 16 + arow) * QPAD + ks * 16 + acol);
                ldmx4(qa[m][ks][0], qa[m][ks][1], qa[m][ks][2], qa[m][ks][3], a);
            }
    }

    const int c2 = 2 * (lane & 3);
    // fragment-ordered bias base for this CTA's row tile / warp / lane
    const uint32_t* bbase = (const uint32_t*)g_biasH
        + (size_t)blockIdx.x * 36 * 2048 + warp * 512 + lane;

    uint32_t o[2][4][2];
    uint32_t rsum2[2][2];
    #pragma unroll
    for (int m = 0; m < 2; m++) {
        #pragma unroll
        for (int n = 0; n < 4; n++) { o[m][n][0] = 0u; o[m][n][1] = 0u; }
        rsum2[m][0] = 0u; rsum2[m][1] = 0u;
    }

    for (int t = 0; t < TPS; t++) {
        // bias -> S accumulators (LDG, coalesced; covered by staging + QK mmas)
        uint32_t S[2][8][2];
        {
            const uint32_t* bt = bbase + (size_t)(tBeg + t) * 2048;
            #pragma unroll
            for (int m = 0; m < 2; m++)
                #pragma unroll
                for (int n = 0; n < 8; n++) {
                    S[m][n][0] = __ldg(bt + (m * 8 + n) * 64);
                    S[m][n][1] = __ldg(bt + (m * 8 + n) * 64 + 32);
                }
        }

        CPA_WAIT0();
        __syncthreads();
        if (t < TPS - 1) issue_tile(tBeg + t + 1, (t + 1) & 1);
        const int s = t & 1;

        // --- S += Q K^T (Q pre-scaled; bias already in S) ---
        {
            const int brow = (lane & 7) + ((lane >> 4) & 1) * 8;
            const int bcol = ((lane >> 3) & 1) * 8;
            #pragma unroll
            for (int np = 0; np < 4; np++) {
                #pragma unroll
                for (int ks = 0; ks < 2; ks++) {
                    uint32_t kf[4];
                    uint32_t a = smem_u32(&Ks[s][(np * 16 + brow) * QPAD + ks * 16 + bcol]);
                    ldmx4(kf[0], kf[1], kf[2], kf[3], a);
                    #pragma unroll
                    for (int m = 0; m < 2; m++) {
                        mma16816h(S[m][2 * np],     qa[m][ks], kf[0], kf[1]);
                        mma16816h(S[m][2 * np + 1], qa[m][ks], kf[2], kf[3]);
                    }
                }
            }
        }

        // --- P = 2^S ; row sums ---
        #pragma unroll
        for (int n = 0; n < 8; n++) {
            #pragma unroll
            for (int m = 0; m < 2; m++) {
                S[m][n][0] = hex2u(S[m][n][0]);
                S[m][n][1] = hex2u(S[m][n][1]);
                rsum2[m][0] = hadd2u(rsum2[m][0], S[m][n][0]);
                rsum2[m][1] = hadd2u(rsum2[m][1], S[m][n][1]);
            }
        }

        // --- O += P @ V ---
        {
            const int vrow = (lane & 7) + ((lane >> 3) & 1) * 8;
            const int vcol = ((lane >> 4) & 1) * 8;
            #pragma unroll
            for (int k2 = 0; k2 < 4; k2++) {
                #pragma unroll
                for (int dp = 0; dp < 2; dp++) {
                    uint32_t vf[4];
                    uint32_t a = smem_u32(&Vs[s][(k2 * 16 + vrow) * QPAD + dp * 16 + vcol]);
                    ldmx4t(vf[0], vf[1], vf[2], vf[3], a);
                    #pragma unroll
                    for (int m = 0; m < 2; m++) {
                        mma16816h(o[m][2 * dp],     &S[m][2 * k2][0], vf[0], vf[1]);
                        mma16816h(o[m][2 * dp + 1], &S[m][2 * k2][0], vf[2], vf[3]);
                    }
                }
            }
        }
    }

    #pragma unroll
    for (int m = 0; m < 2; m++)
        #pragma unroll
        for (int rr = 0; rr < 2; rr++) {
            float2 f = h2f2(rsum2[m][rr]);
            float sv = f.x + f.y;
            sv += __shfl_xor_sync(0xFFFFFFFF, sv, 1);
            sv += __shfl_xor_sync(0xFFFFFFFF, sv, 2);
            if ((lane & 3) == 0) {
                const int grow = rowBase + warp * 32 + m * 16 + (lane >> 2) + rr * 8;
                g_rsP[(size_t)z * (BB * NH * HWP) + (size_t)(b * NH + h) * HWP + grow] = sv;
            }
        }

    #pragma unroll
    for (int m = 0; m < 2; m++)
        #pragma unroll
        for (int rr = 0; rr < 2; rr++) {
            const int grow = rowBase + warp * 32 + m * 16 + (lane >> 2) + rr * 8;
            __half* od = g_Oph + (size_t)z * (BB * HWP * DM) + (size_t)(b * HWP + grow) * DM + h * DK;
            #pragma unroll
            for (int n = 0; n < 4; n++)
                *(uint32_t*)(od + n * 8 + c2) = o[m][n][rr];
        }
}

// ---------------------------------------------------------------------------
// Kernel 3: HMMA output projection + residual, fused KV-split combine
// (unchanged from R13).
// ---------------------------------------------------------------------------
__global__ __launch_bounds__(256) void outproj_mma_kernel(
    const float* __restrict__ x, const float* __restrict__ bo,
    const float* __restrict__ gamma_p, float* __restrict__ out)
{
    __shared__ __align__(16) __half ws2[2][64 * QPAD];
    __shared__ __align__(16) __half os2[2][64 * QPAD];

    const int tid  = threadIdx.x;
    const int warp = tid >> 5;
    const int lane = tid & 31;

    const int gp    = blockIdx.x * 64;
    const int b     = gp / HWP;
    const int pb    = gp - b * HWP;
    const int cBase = blockIdx.y * 64;
    const float gamma = *gamma_p;

    const uint32_t wsA = smem_u32(ws2);

    auto load_w = [&](int s, int k0) {
        const char* wb = (const char*)g_Woh + ((size_t)cBase * DM + k0) * 2;
        const int r = tid >> 2, q = tid & 3;
        CPA16(wsA + s * 5120 + r * 80 + q * 16, wb + (size_t)r * (DM * 2) + q * 16);
        CPA_COMMIT();
    };

    const int orow = tid >> 2;
    const int oq   = tid & 3;
    auto load_o = [&](int k0, uint4& a0, uint4& a1, float& inv) {
        const int hh = k0 >> 5;
        const size_t base = (size_t)(b * HWP + pb + orow) * DM + k0 + oq * 8;
        a0 = *(const uint4*)(g_Oph + base);
        a1 = *(const uint4*)(g_Oph + (size_t)(BB * HWP * DM) + base);
        const size_t rsi = (size_t)(b * NH + hh) * HWP + pb + orow;
        inv = __fdividef(1.0f, g_rsP[rsi] + g_rsP[(size_t)(BB * NH * HWP) + rsi]);
    };
    auto store_o = [&](int s, uint4 a0, uint4 a1, float inv) {
        const uint32_t iv = f2h2(inv, inv);
        uint4 r;
        r.x = hmul2u(hadd2u(a0.x, a1.x), iv);
        r.y = hmul2u(hadd2u(a0.y, a1.y), iv);
        r.z = hmul2u(hadd2u(a0.z, a1.z), iv);
        r.w = hmul2u(hadd2u(a0.w, a1.w), iv);
        *(uint4*)(&os2[s][orow * QPAD + oq * 8]) = r;
    };

    const int cw = warp >> 2;
    const int pw = warp & 3;

    float acc[2][2][4] = {};

    load_w(0, 0);
    uint4 oa0, oa1;
    float oinv;
    load_o(0, oa0, oa1, oinv);

    for (int c = 0; c < 8; c++) {
        CPA_WAIT0();
        __syncthreads();
        const int s = c & 1;
        store_o(s, oa0, oa1, oinv);
        if (c < 7) {
            load_w((c + 1) & 1, (c + 1) * 32);
            load_o((c + 1) * 32, oa0, oa1, oinv);
        }
        __syncthreads();

        const int arow = (lane & 7) + ((lane >> 3) & 1) * 8;
        const int acol = (lane >> 4) * 8;
        const int brow = (lane & 7) + ((lane >> 4) & 1) * 8;
        const int bcol = ((lane >> 3) & 1) * 8;

        #pragma unroll
        for (int ks = 0; ks < 2; ks++) {
            uint32_t af[2][4];
            #pragma unroll
            for (int mt = 0; mt < 2; mt++) {
                uint32_t a = smem_u32(&ws2[s][(cw * 32 + mt * 16 + arow) * QPAD + ks * 16 + acol]);
                ldmx4(af[mt][0], af[mt][1], af[mt][2], af[mt][3], a);
            }
            uint32_t bf[4];
            uint32_t a = smem_u32(&os2[s][(pw * 16 + brow) * QPAD + ks * 16 + bcol]);
            ldmx4(bf[0], bf[1], bf[2], bf[3], a);
            #pragma unroll
            for (int mt = 0; mt < 2; mt++) {
                mma16816f(acc[mt][0], af[mt], bf);
                mma16816f(acc[mt][1], af[mt], bf + 2);
            }
        }
    }

    const int c2 = 2 * (lane & 3);
    #pragma unroll
    for (int mt = 0; mt < 2; mt++) {
        #pragma unroll
        for (int rr = 0; rr < 2; rr++) {
            const int c = cBase + cw * 32 + mt * 16 + (lane >> 2) + rr * 8;
            const float bias = bo[c];
            #pragma unroll
            for (int nt = 0; nt < 2; nt++) {
                const int p = pb + pw * 16 + nt * 8 + c2;
                const size_t idx = (size_t)b * CC * HWP + (size_t)c * HWP + p;
                float2 xv = *(const float2*)(x + idx);
                float2 r;
                r.x = xv.x + gamma * acc[mt][nt][rr * 2 + 0] + bias;
                r.y = xv.y + gamma * acc[mt][nt][rr * 2 + 1] + bias;
                *(float2*)(out + idx) = r;
            }
        }
    }
}

// ---------------------------------------------------------------------------
extern "C" void kernel_launch(void* const* d_in, const int* in_sizes, int n_in,
                              void* d_out, int out_size)
{
    (void)in_sizes; (void)n_in; (void)out_size;
    const float* x   = (const float*)d_in[0];
    const float* Wq  = (const float*)d_in[1];
    const float* bq  = (const float*)d_in[2];
    const float* Wk  = (const float*)d_in[3];
    const float* bk  = (const float*)d_in[4];
    const float* Wv  = (const float*)d_in[5];
    const float* bv  = (const float*)d_in[6];
    const float* Wo  = (const float*)d_in[7];
    const float* bo  = (const float*)d_in[8];
    const float* lam = (const float*)d_in[9];
    const float* gam = (const float*)d_in[10];
    float* out = (float*)d_out;

    prep_kernel<<<548, 256>>>(lam, Wq, Wk, Wv, Wo);
    bias_fill_kernel<<<(HWP * HWP / 2) / 256, 256>>>();
    xt_kernel<<<dim3(HWP / 64, CC / 64, BB), 256>>>(x);

    qkv_mma_kernel<<<dim3(BB * HWP / 64, DM / 64), 256>>>(bq, bk, bv);

    attn_mma_kernel<<<dim3(HWP / 128, BB * NH, NSPLIT), 128>>>();

    outproj_mma_kernel<<<dim3(BB * HWP / 64, CC / 64), 256>>>(x, bo, gam, out);
}